// round 9
// baseline (speedup 1.0000x reference)
#include <cuda_runtime.h>
#include <cuda_fp16.h>
#include <cstdint>

#define BATCH    128
#define NPTS     16384
#define GL       48
#define GW       20
#define GH       18
#define SLAB     (GL * GW * GH)        // 17280 voxels
#define HALF_L   2.4f
#define HALF_W   1.0f

#define THREADS    512
#define GRID_CTAS  592                 // 148 SMs * 4 CTAs, one exact wave
#define SMEM_BYTES (SLAB * 2)          // e4m3 z-pair table = 34560 B

// pack (cur, next) as e4m3x2: low byte = cur, high byte = next
__device__ __forceinline__ uint32_t pack_e4m3(float cur, float nxt) {
    uint32_t r;
    asm("{\n\t.reg .b16 t;\n\t"
        "cvt.rn.satfinite.e4m3x2.f32 t, %1, %2;\n\t"
        "cvt.u32.u16 %0, t;\n\t}"
        : "=r"(r) : "f"(nxt), "f"(cur));
    return r;
}

// decode e4m3 pair -> (float cur, float next)
__device__ __forceinline__ float2 unpack_e4m3(uint16_t v) {
    uint32_t h2;
    asm("{\n\t.reg .b16 t;\n\t"
        "mov.b16 t, %1;\n\t"
        "cvt.rn.f16x2.e4m3x2 %0, t;\n\t}"
        : "=r"(h2) : "h"(v));
    __half2 hh = *reinterpret_cast<__half2*>(&h2);
    return __half22float2(hh);
}

__global__ __launch_bounds__(THREADS, 4)
void pose_loss_kernel(const float* __restrict__ voxels,
                      const float* __restrict__ pts,
                      const float* __restrict__ hgt,
                      float* __restrict__ out)
{
    extern __shared__ uint16_t svox[];   // svox[i] = e4m3(v[i]) | e4m3(v[i+1 or i if z==17])<<8
    __shared__ float warp_red[THREADS / 32];

    const int g   = blockIdx.x;
    const int tid = threadIdx.x;

    // ---- work assignment: batches 0..79 -> 5 CTAs, 80..127 -> 4 CTAs ----
    int batch, rank, nch;
    if (g < 400) { batch = g / 5;          rank = g % 5;          nch = 5; }
    else         { batch = 80 + (g - 400) / 4; rank = (g - 400) % 4; nch = 4; }
    const int pstart = (rank * NPTS / nch) & ~3;
    const int pend   = (rank == nch - 1) ? NPTS : (((rank + 1) * NPTS / nch) & ~3);

    const float*  __restrict__ vsrc  = voxels + (size_t)batch * SLAB;
    const float4* __restrict__ vsrc4 = (const float4*)vsrc;

    // ---- stage e4m3 z-pair slab (single pass, coalesced) ----
    for (int i = tid; i < SLAB / 4; i += THREADS) {
        const int i4 = i * 4;
        const float4 a = vsrc4[i];
        int nidx = i4 + 4; if (nidx >= SLAB) nidx = SLAB - 1;
        const float nxt = vsrc[nidx];
        const int mz = (i4 + 1) % GH;           // z(i4)==17 <=> mz==0, etc.
        const float n0 = (mz == 0)  ? a.x : a.y;
        const float n1 = (mz == 17) ? a.y : a.z;
        const float n2 = (mz == 16) ? a.z : a.w;
        const float n3 = (mz == 15) ? a.w : nxt;

        uint2 pk;
        pk.x = pack_e4m3(a.x, n0) | (pack_e4m3(a.y, n1) << 16);
        pk.y = pack_e4m3(a.z, n2) | (pack_e4m3(a.w, n3) << 16);
        *(uint2*)&svox[i4] = pk;                // 8B-aligned store
    }
    __syncthreads();

    float acc = 0.0f;
    const size_t bbase = (size_t)batch * NPTS;

    for (int p = pstart + tid * 4; p < pend; p += THREADS * 4) {
        const size_t gp = bbase + p;
        // 4 points * 3 floats = 48B = 3x float4 (aligned: p % 4 == 0)
        const float4* __restrict__ pf = (const float4*)(pts + gp * 3);
        const float4 a = pf[0], b = pf[1], c = pf[2];
        const float4 h = *(const float4*)(hgt + gp);

        const float PX[4] = { a.x, a.w, b.z, c.y };
        const float PY[4] = { a.y, b.x, b.w, c.z };
        const float PZ[4] = { a.z, b.y, c.x, c.w };
        const float HH[4] = { h.x, h.y, h.z, h.w };

        #pragma unroll
        for (int k = 0; k < 4; ++k) {
            const float x = PX[k] + HALF_L;
            const float y = PY[k] + HALF_W;
            const float z = PZ[k] + HH[k] * 0.5f;

            const int ix = __float2int_rd(x * 10.0f);
            const int iy = __float2int_rd(y * 10.0f);
            const int iz = __float2int_rd(z * 10.0f);

            // t = (l+1)/2 folded to (x - xm*0.1)*10
            const float tx = (x - (float)ix * 0.1f) * 10.0f;
            const float ty = (y - (float)iy * 0.1f) * 10.0f;
            const float tz = (z - (float)iz * 0.1f) * 10.0f;

            const int x0 = min(max(ix, 0), GL - 1);
            const int y0 = min(max(iy, 0), GW - 1);
            const int zp = min(max(iz, 0), GH - 1);
            const int x1 = min(x0 + 1, GL - 1);
            const int y1 = min(y0 + 1, GW - 1);

            // lower clamp: zeroing t reproduces ref's corner0==corner1 exactly
            const float txp = (ix < 0) ? 0.0f : tx;
            const float typ = (iy < 0) ? 0.0f : ty;
            const float tzp = (iz < 0) ? 0.0f : tz;
            const float sxp = 1.0f - txp;
            const float syp = 1.0f - typ;
            const float szp = 1.0f - tzp;

            const int r0 = x0 * GW, r1 = x1 * GW;
            const float2 f00 = unpack_e4m3(svox[(r0 + y0) * GH + zp]);
            const float2 f01 = unpack_e4m3(svox[(r0 + y1) * GH + zp]);
            const float2 f10 = unpack_e4m3(svox[(r1 + y0) * GH + zp]);
            const float2 f11 = unpack_e4m3(svox[(r1 + y1) * GH + zp]);

            const float v00 = fmaf(f00.y, tzp, f00.x * szp);
            const float v01 = fmaf(f01.y, tzp, f01.x * szp);
            const float v10 = fmaf(f10.y, tzp, f10.x * szp);
            const float v11 = fmaf(f11.y, tzp, f11.x * szp);

            const float vx1 = fmaf(v11, typ, v10 * syp);
            const float vx0 = fmaf(v01, typ, v00 * syp);
            const float sdf = fmaf(vx1, txp, vx0 * sxp);

            const float ax = fabsf(sdf);
            acc += (ax < 1.0f) ? (0.5f * sdf * sdf) : (ax - 0.5f);
        }
    }

    // ---- block reduction ----
    #pragma unroll
    for (int off = 16; off > 0; off >>= 1)
        acc += __shfl_xor_sync(0xFFFFFFFFu, acc, off);

    const int lane = tid & 31;
    const int wid  = tid >> 5;
    if (lane == 0) warp_red[wid] = acc;
    __syncthreads();

    if (wid == 0) {
        float s = (lane < THREADS / 32) ? warp_red[lane] : 0.0f;
        #pragma unroll
        for (int off = 8; off > 0; off >>= 1)
            s += __shfl_xor_sync(0xFFFFFFFFu, s, off);
        if (lane == 0)
            atomicAdd(out, s * (1.0f / ((float)BATCH * (float)NPTS)));
    }
}

extern "C" void kernel_launch(void* const* d_in, const int* in_sizes, int n_in,
                              void* d_out, int out_size)
{
    const float* voxels = (const float*)d_in[0];
    const float* pts    = (const float*)d_in[1];
    const float* hgt    = (const float*)d_in[2];
    float* out          = (float*)d_out;

    cudaMemsetAsync(out, 0, sizeof(float));

    pose_loss_kernel<<<GRID_CTAS, THREADS, SMEM_BYTES>>>(voxels, pts, hgt, out);
}

// round 11
// speedup vs baseline: 1.6214x; 1.6214x over previous
#include <cuda_runtime.h>
#include <cuda_fp16.h>

#define BATCH    128
#define NPTS     16384
#define GL       48
#define GW       20
#define GH       18
#define SLAB     (GL * GW * GH)        // 17280 voxels; half2 pair slab = 69120 B
#define HALF_L   2.4f
#define HALF_W   1.0f

#define THREADS    1024
#define GRID_CTAS  296                 // 148 SMs * 2 CTAs, one exact wave
#define SMEM_BYTES (SLAB * 4)          // half2 z-pair table

__global__ __launch_bounds__(THREADS, 2)
void pose_loss_kernel(const float* __restrict__ voxels,
                      const float* __restrict__ pts,
                      const float* __restrict__ hgt,
                      float* __restrict__ out)
{
    extern __shared__ __half2 svox[];  // svox[i] = (v[i], v[i+1 or i if z==17])
    __shared__ float warp_red[THREADS / 32];

    const int g   = blockIdx.x;
    const int tid = threadIdx.x;

    // ---- balanced work split: batches 0..39 -> 3 CTAs, 40..127 -> 2 CTAs ----
    int batch, rank, nch;
    if (g < 120) { batch = g / 3;             rank = g % 3;         nch = 3; }
    else         { batch = 40 + (g - 120) / 2; rank = (g - 120) % 2; nch = 2; }
    const int pstart = (rank * NPTS / nch) & ~3;
    const int pend   = (rank == nch - 1) ? NPTS : (((rank + 1) * NPTS / nch) & ~3);

    const float* __restrict__ vsrc = voxels + (size_t)batch * SLAB;

    // ---- stage half2 z-pair slab into shared (coalesced float4 reads) ----
    {
        const float4* __restrict__ vsrc4 = (const float4*)vsrc;
        for (int i = tid; i < SLAB / 4; i += THREADS) {
            const int i4 = i * 4;
            const float4 a = vsrc4[i];
            int nidx = i4 + 4; if (nidx >= SLAB) nidx = SLAB - 1;
            const float nxt = vsrc[nidx];
            // pair partner = next element along z, unless z==17 (then itself)
            const int mz = (i4 + 1) % GH;   // z(i4)==17 <=> mz==0, etc.
            const float n0 = (mz == 0)  ? a.x : a.y;
            const float n1 = (mz == 17) ? a.y : a.z;
            const float n2 = (mz == 16) ? a.z : a.w;
            const float n3 = (mz == 15) ? a.w : nxt;
            svox[i4 + 0] = __floats2half2_rn(a.x, n0);
            svox[i4 + 1] = __floats2half2_rn(a.y, n1);
            svox[i4 + 2] = __floats2half2_rn(a.z, n2);
            svox[i4 + 3] = __floats2half2_rn(a.w, n3);
        }
    }
    __syncthreads();

    float acc = 0.0f;
    const size_t bbase = (size_t)batch * NPTS;

    for (int p = pstart + tid * 4; p < pend; p += THREADS * 4) {
        const size_t gp = bbase + p;
        // 4 points * 3 floats = 48B = 3x float4 (p % 4 == 0 -> 16B aligned)
        const float4* __restrict__ pf = (const float4*)(pts + gp * 3);
        const float4 a = pf[0], b = pf[1], c = pf[2];
        const float4 h = *(const float4*)(hgt + gp);

        const float PX[4] = { a.x, a.w, b.z, c.y };
        const float PY[4] = { a.y, b.x, b.w, c.z };
        const float PZ[4] = { a.z, b.y, c.x, c.w };
        const float HH[4] = { h.x, h.y, h.z, h.w };

        #pragma unroll
        for (int k = 0; k < 4; ++k) {
            const float x = PX[k] + HALF_L;
            const float y = PY[k] + HALF_W;
            const float z = PZ[k] + HH[k] * 0.5f;

            const int ix = __float2int_rd(x * 10.0f);
            const int iy = __float2int_rd(y * 10.0f);
            const int iz = __float2int_rd(z * 10.0f);

            // t = (l+1)/2 folded to (x - xm*0.1)*10
            const float tx = (x - (float)ix * 0.1f) * 10.0f;
            const float ty = (y - (float)iy * 0.1f) * 10.0f;
            const float tz = (z - (float)iz * 0.1f) * 10.0f;

            const int x0 = min(max(ix, 0), GL - 1);
            const int y0 = min(max(iy, 0), GW - 1);
            const int zp = min(max(iz, 0), GH - 1);
            const int x1 = min(x0 + 1, GL - 1);
            const int y1 = min(y0 + 1, GW - 1);

            // lower clamp: zeroing t reproduces ref's corner0==corner1 exactly
            const float txp = (ix < 0) ? 0.0f : tx;
            const float typ = (iy < 0) ? 0.0f : ty;
            const float tzp = (iz < 0) ? 0.0f : tz;
            const float sxp = 1.0f - txp;
            const float syp = 1.0f - typ;
            const float szp = 1.0f - tzp;

            const int r0 = x0 * GW, r1 = x1 * GW;
            const float2 f00 = __half22float2(svox[(r0 + y0) * GH + zp]);
            const float2 f01 = __half22float2(svox[(r0 + y1) * GH + zp]);
            const float2 f10 = __half22float2(svox[(r1 + y0) * GH + zp]);
            const float2 f11 = __half22float2(svox[(r1 + y1) * GH + zp]);

            const float v00 = fmaf(f00.y, tzp, f00.x * szp);
            const float v01 = fmaf(f01.y, tzp, f01.x * szp);
            const float v10 = fmaf(f10.y, tzp, f10.x * szp);
            const float v11 = fmaf(f11.y, tzp, f11.x * szp);

            const float vx1 = fmaf(v11, typ, v10 * syp);
            const float vx0 = fmaf(v01, typ, v00 * syp);
            const float sdf = fmaf(vx1, txp, vx0 * sxp);

            const float ax = fabsf(sdf);
            acc += (ax < 1.0f) ? (0.5f * sdf * sdf) : (ax - 0.5f);
        }
    }

    // ---- block reduction ----
    #pragma unroll
    for (int off = 16; off > 0; off >>= 1)
        acc += __shfl_xor_sync(0xFFFFFFFFu, acc, off);

    const int lane = tid & 31;
    const int wid  = tid >> 5;
    if (lane == 0) warp_red[wid] = acc;
    __syncthreads();

    if (wid == 0) {
        float s = (lane < THREADS / 32) ? warp_red[lane] : 0.0f;
        #pragma unroll
        for (int off = 16; off > 0; off >>= 1)
            s += __shfl_xor_sync(0xFFFFFFFFu, s, off);
        if (lane == 0)
            atomicAdd(out, s * (1.0f / ((float)BATCH * (float)NPTS)));
    }
}

extern "C" void kernel_launch(void* const* d_in, const int* in_sizes, int n_in,
                              void* d_out, int out_size)
{
    const float* voxels = (const float*)d_in[0];
    const float* pts    = (const float*)d_in[1];
    const float* hgt    = (const float*)d_in[2];
    float* out          = (float*)d_out;

    static int configured = 0;
    if (!configured) {
        cudaFuncSetAttribute(pose_loss_kernel,
                             cudaFuncAttributeMaxDynamicSharedMemorySize,
                             SMEM_BYTES);
        configured = 1;
    }

    cudaMemsetAsync(out, 0, sizeof(float));

    pose_loss_kernel<<<GRID_CTAS, THREADS, SMEM_BYTES>>>(voxels, pts, hgt, out);
}

// round 12
// speedup vs baseline: 1.6733x; 1.0321x over previous
#include <cuda_runtime.h>
#include <cuda_fp16.h>

#define BATCH    128
#define NPTS     16384
#define GL       48
#define GW       20
#define GH       18
#define SLAB     (GL * GW * GH)        // 17280 source voxels
#define HALF_L   2.4f
#define HALF_W   1.0f

// padded pair table: x in [0,48], y in [0,20], z in [0,17]
#define PY       (GW + 1)              // 21
#define XSTRIDE  (PY * GH)             // 378
#define PSLAB    ((GL + 1) * XSTRIDE)  // 18522 half2 entries

#define THREADS    1024
#define GRID_CTAS  296                 // 148 SMs * 2 CTAs, one exact wave
#define SMEM_BYTES (PSLAB * 4)         // 74088 B

__global__ __launch_bounds__(THREADS, 2)
void pose_loss_kernel(const float* __restrict__ voxels,
                      const float* __restrict__ pts,
                      const float* __restrict__ hgt,
                      float* __restrict__ out)
{
    extern __shared__ __half2 svox[];  // svox[(x*21+y)*18+z] = (v[z], v[z+1 or z if z==17])
    __shared__ float warp_red[THREADS / 32];

    const int g   = blockIdx.x;
    const int tid = threadIdx.x;

    // ---- balanced split: batches 0..39 -> 3 CTAs, 40..127 -> 2 CTAs ----
    int batch, rank, nch;
    if (g < 120) { batch = g / 3;             rank = g % 3;         nch = 3; }
    else         { batch = 40 + (g - 120) / 2; rank = (g - 120) % 2; nch = 2; }
    const int pstart = (rank * NPTS / nch) & ~3;
    const int pend   = (rank == nch - 1) ? NPTS : (((rank + 1) * NPTS / nch) & ~3);

    const float* __restrict__ vsrc = voxels + (size_t)batch * SLAB;

    // ---- stage z-pair slab into padded layout (coalesced float4 reads) ----
    {
        const float4* __restrict__ vsrc4 = (const float4*)vsrc;
        for (int i = tid; i < SLAB / 4; i += THREADS) {
            const int i4 = i * 4;
            const int xs  = i4 / (GW * GH);          // 360 elems per x-slice
            const int rem = i4 - xs * (GW * GH);
            const int dst = xs * XSTRIDE + rem;      // float4 never crosses x (360%4==0)

            const float4 a = vsrc4[i];
            int nidx = i4 + 4; if (nidx >= SLAB) nidx = SLAB - 1;
            const float nxt = vsrc[nidx];
            const int mz = (i4 + 1) % GH;            // z(i4)==17 <=> mz==0, etc.
            const float n0 = (mz == 0)  ? a.x : a.y;
            const float n1 = (mz == 17) ? a.y : a.z;
            const float n2 = (mz == 16) ? a.z : a.w;
            const float n3 = (mz == 15) ? a.w : nxt;
            svox[dst + 0] = __floats2half2_rn(a.x, n0);
            svox[dst + 1] = __floats2half2_rn(a.y, n1);
            svox[dst + 2] = __floats2half2_rn(a.z, n2);
            svox[dst + 3] = __floats2half2_rn(a.w, n3);
        }
    }
    __syncthreads();

    // ---- y-pad: row y=20 := row y=19 for x in [0,48) ----
    for (int i = tid; i < GL * GH; i += THREADS) {
        const int xs = i / GH, z = i - xs * GH;
        svox[xs * XSTRIDE + GW * GH + z] = svox[xs * XSTRIDE + (GW - 1) * GH + z];
    }
    __syncthreads();

    // ---- x-pad: slice x=48 := slice x=47 (incl. padded y row) ----
    for (int j = tid; j < XSTRIDE; j += THREADS)
        svox[GL * XSTRIDE + j] = svox[(GL - 1) * XSTRIDE + j];
    __syncthreads();

    float acc = 0.0f;
    const size_t bbase = (size_t)batch * NPTS;

    for (int p = pstart + tid * 4; p < pend; p += THREADS * 4) {
        const size_t gp = bbase + p;
        const float4* __restrict__ pf = (const float4*)(pts + gp * 3);
        const float4 a = pf[0], b = pf[1], c = pf[2];
        const float4 h = *(const float4*)(hgt + gp);

        const float PX[4] = { a.x, a.w, b.z, c.y };
        const float PY4[4] = { a.y, b.x, b.w, c.z };
        const float PZ[4] = { a.z, b.y, c.x, c.w };
        const float HH[4] = { h.x, h.y, h.z, h.w };

        #pragma unroll
        for (int k = 0; k < 4; ++k) {
            const float xf = (PX[k] + HALF_L) * 10.0f;
            const float yf = (PY4[k] + HALF_W) * 10.0f;
            const float zf = fmaf(HH[k], 0.5f, PZ[k]) * 10.0f;

            const float xmf = floorf(xf);
            const float ymf = floorf(yf);
            const float zmf = floorf(zf);

            const float tx = xf - xmf;
            const float ty = yf - ymf;
            const float tz = zf - zmf;

            const int ix = (int)xmf;
            const int iy = (int)ymf;
            const int iz = (int)zmf;

            const int x0 = min(max(ix, 0), GL - 1);
            const int y0 = min(max(iy, 0), GW - 1);
            const int zp = min(max(iz, 0), GH - 1);

            // lower clamp: zeroing t reproduces ref's corner0==corner1 exactly
            const float txp = (ix < 0) ? 0.0f : tx;
            const float typ = (iy < 0) ? 0.0f : ty;
            const float tzp = (iz < 0) ? 0.0f : tz;
            const float sxp = 1.0f - txp;
            const float syp = 1.0f - typ;
            const float szp = 1.0f - tzp;

            // padded layout: x1=x0+1, y1=y0+1 always valid
            const int c00 = (x0 * PY + y0) * GH + zp;
            const __half2 h00 = svox[c00];
            const __half2 h01 = svox[c00 + GH];
            const __half2 h10 = svox[c00 + XSTRIDE];
            const __half2 h11 = svox[c00 + XSTRIDE + GH];

            const __half2 w00 = __float2half2_rn(sxp * syp);
            const __half2 w01 = __float2half2_rn(sxp * typ);
            const __half2 w10 = __float2half2_rn(txp * syp);
            const __half2 w11 = __float2half2_rn(txp * typ);

            __half2 acc2 = __hmul2(h00, w00);
            acc2 = __hfma2(h01, w01, acc2);
            acc2 = __hfma2(h10, w10, acc2);
            acc2 = __hfma2(h11, w11, acc2);

            const float2 fa = __half22float2(acc2);
            const float sdf = fmaf(fa.y, tzp, fa.x * szp);

            const float ax = fabsf(sdf);
            acc += (ax < 1.0f) ? (0.5f * sdf * sdf) : (ax - 0.5f);
        }
    }

    // ---- block reduction ----
    #pragma unroll
    for (int off = 16; off > 0; off >>= 1)
        acc += __shfl_xor_sync(0xFFFFFFFFu, acc, off);

    const int lane = tid & 31;
    const int wid  = tid >> 5;
    if (lane == 0) warp_red[wid] = acc;
    __syncthreads();

    if (wid == 0) {
        float s = (lane < THREADS / 32) ? warp_red[lane] : 0.0f;
        #pragma unroll
        for (int off = 16; off > 0; off >>= 1)
            s += __shfl_xor_sync(0xFFFFFFFFu, s, off);
        if (lane == 0)
            atomicAdd(out, s * (1.0f / ((float)BATCH * (float)NPTS)));
    }
}

extern "C" void kernel_launch(void* const* d_in, const int* in_sizes, int n_in,
                              void* d_out, int out_size)
{
    const float* voxels = (const float*)d_in[0];
    const float* pts    = (const float*)d_in[1];
    const float* hgt    = (const float*)d_in[2];
    float* out          = (float*)d_out;

    static int configured = 0;
    if (!configured) {
        cudaFuncSetAttribute(pose_loss_kernel,
                             cudaFuncAttributeMaxDynamicSharedMemorySize,
                             SMEM_BYTES);
        configured = 1;
    }

    cudaMemsetAsync(out, 0, sizeof(float));

    pose_loss_kernel<<<GRID_CTAS, THREADS, SMEM_BYTES>>>(voxels, pts, hgt, out);
}